// round 1
// baseline (speedup 1.0000x reference)
#include <cuda_runtime.h>

// QuantumRegression: 10-wire statevector simulator, one CTA per batch sample.
// State: 1024 complex64 amplitudes in shared memory.
// wire w <-> bit position (9-w) of the state index (stride 2^(9-w)).

#define NW 10
#define DIM 1024
#define NT 512

__device__ __forceinline__ int pair_i0(int t, int p) {
    // insert a zero bit at position p into the 9-bit value t
    int low = t & ((1 << p) - 1);
    return ((t >> p) << (p + 1)) | low;
}

// suffix-parity permutation = composition of CNOT(w), w=0..8 (adjacent chain)
__device__ __forceinline__ int cnot_chain_perm(int i) {
    i ^= i >> 1;
    i ^= i >> 2;
    i ^= i >> 4;
    i ^= i >> 8;
    return i;  // bits >=10 are zero for i < 1024
}

__global__ __launch_bounds__(NT) void qreg_kernel(
    const float* __restrict__ x,       // (B, 10)
    const float* __restrict__ params,  // (2*10*3,)
    const float* __restrict__ head_w,  // (20,)
    const float* __restrict__ head_b,  // (1,)
    float* __restrict__ out)           // (B,)
{
    __shared__ float2 st[DIM];
    __shared__ float  swz[2 * NW];     // head weights: [0..9]=Z, [10..19]=X
    __shared__ float  red[NT / 32];

    const int b = blockIdx.x;
    const int t = threadIdx.x;

    // init |0...0>
    st[t]       = make_float2(0.f, 0.f);
    st[t + 512] = make_float2(0.f, 0.f);
    if (t == 0) st[0] = make_float2(1.f, 0.f);
    if (t < 2 * NW) swz[t] = head_w[t];
    __syncthreads();

    // ---- RY encoding (batched angles) : real 2x2 gates ----
    #pragma unroll
    for (int w = 0; w < NW; ++w) {
        float c, s;
        __sincosf(0.5f * x[b * NW + w], &s, &c);
        const int p  = 9 - w;
        const int i0 = pair_i0(t, p);
        const int i1 = i0 | (1 << p);
        float2 a0 = st[i0], a1 = st[i1];
        // [c -s; s c] acting on (a0, a1), component-wise on re/im
        st[i0] = make_float2(c * a0.x - s * a1.x, c * a0.y - s * a1.y);
        st[i1] = make_float2(s * a0.x + c * a1.x, s * a0.y + c * a1.y);
        __syncthreads();
    }

    // ---- 2 layers of (Rot on each wire, then fused CNOT chain) ----
    #pragma unroll
    for (int l = 0; l < 2; ++l) {
        #pragma unroll
        for (int w = 0; w < NW; ++w) {
            const float phi   = params[(l * NW + w) * 3 + 0];
            const float theta = params[(l * NW + w) * 3 + 1];
            const float omega = params[(l * NW + w) * 3 + 2];
            float ct, stt, cp, sp, cm, sm;
            __sincosf(0.5f * theta, &stt, &ct);
            __sincosf(0.5f * (phi + omega), &sp, &cp);
            __sincosf(0.5f * (phi - omega), &sm, &cm);
            // Rot = RZ(omega) RY(theta) RZ(phi):
            // U00 = ct * e^{-i(phi+omega)/2}
            // U01 = -stt * e^{+i(phi-omega)/2}
            // U10 =  stt * e^{-i(phi-omega)/2}
            // U11 = ct * e^{+i(phi+omega)/2}
            const float u00r =  ct * cp,  u00i = -ct * sp;
            const float u01r = -stt * cm, u01i = -stt * sm;
            const float u10r =  stt * cm, u10i = -stt * sm;
            const float u11r =  ct * cp,  u11i =  ct * sp;

            const int p  = 9 - w;
            const int i0 = pair_i0(t, p);
            const int i1 = i0 | (1 << p);
            float2 a0 = st[i0], a1 = st[i1];
            float2 n0, n1;
            n0.x = u00r * a0.x - u00i * a0.y + u01r * a1.x - u01i * a1.y;
            n0.y = u00r * a0.y + u00i * a0.x + u01r * a1.y + u01i * a1.x;
            n1.x = u10r * a0.x - u10i * a0.y + u11r * a1.x - u11i * a1.y;
            n1.y = u10r * a0.y + u10i * a0.x + u11r * a1.y + u11i * a1.x;
            st[i0] = n0;
            st[i1] = n1;
            __syncthreads();
        }
        // fused CNOT chain: single permutation pass
        {
            const int ia = t, ib = t + 512;
            float2 va = st[ia], vb = st[ib];
            const int ja = cnot_chain_perm(ia);
            const int jb = cnot_chain_perm(ib);
            __syncthreads();
            st[ja] = va;
            st[jb] = vb;
            __syncthreads();
        }
    }

    // ---- fused feature extraction + linear head ----
    float partial = 0.f;

    // <Z_w> contributions: each thread handles its own 2 amplitudes
    #pragma unroll
    for (int k = 0; k < 2; ++k) {
        const int i = t + k * 512;
        const float2 a = st[i];
        const float pr = a.x * a.x + a.y * a.y;
        float sgn_sum = 0.f;
        #pragma unroll
        for (int w = 0; w < NW; ++w) {
            const float wz = swz[w];
            sgn_sum += ((i >> (9 - w)) & 1) ? -wz : wz;
        }
        partial += pr * sgn_sum;
    }

    // <X_w> contributions: 2*Re(conj(a0)*a1) per butterfly pair
    #pragma unroll
    for (int w = 0; w < NW; ++w) {
        const int p  = 9 - w;
        const int i0 = pair_i0(t, p);
        const int i1 = i0 | (1 << p);
        const float2 a0 = st[i0], a1 = st[i1];
        partial += 2.f * swz[NW + w] * (a0.x * a1.x + a0.y * a1.y);
    }

    // block reduction (512 -> 1)
    #pragma unroll
    for (int off = 16; off > 0; off >>= 1)
        partial += __shfl_down_sync(0xffffffffu, partial, off);
    if ((t & 31) == 0) red[t >> 5] = partial;
    __syncthreads();
    if (t < 16) {
        float v = red[t];
        #pragma unroll
        for (int off = 8; off > 0; off >>= 1)
            v += __shfl_down_sync(0x0000ffffu, v, off);
        if (t == 0) out[b] = v + head_b[0];
    }
}

extern "C" void kernel_launch(void* const* d_in, const int* in_sizes, int n_in,
                              void* d_out, int out_size) {
    const float* x      = (const float*)d_in[0];  // (B,10)
    const float* params = (const float*)d_in[1];  // (60,)
    const float* hw     = (const float*)d_in[2];  // (20,)
    const float* hb     = (const float*)d_in[3];  // (1,)
    float* out = (float*)d_out;
    const int B = in_sizes[0] / NW;               // 4096
    qreg_kernel<<<B, NT>>>(x, params, hw, hb, out);
}

// round 3
// speedup vs baseline: 2.4676x; 2.4676x over previous
#include <cuda_runtime.h>

#define FULL 0xffffffffu
#define NW 10

// Precomputed Rot matrices: per gate 8 floats {u00r,u00i,u01r,u01i,u10r,u10i,u11r,u11i}
__device__ float g_rot[2 * NW * 8];

__global__ void prep_kernel(const float* __restrict__ params) {
    int g = threadIdx.x;
    if (g < 2 * NW) {
        float phi = params[g * 3 + 0], th = params[g * 3 + 1], om = params[g * 3 + 2];
        float ct, st, cp, sp, cm, sm;
        sincosf(0.5f * th, &st, &ct);
        sincosf(0.5f * (phi + om), &sp, &cp);
        sincosf(0.5f * (phi - om), &sm, &cm);
        float* o = &g_rot[g * 8];
        // Rot = RZ(om) RY(th) RZ(phi)
        o[0] =  ct * cp;  o[1] = -ct * sp;   // u00
        o[2] = -st * cm;  o[3] = -st * sm;   // u01
        o[4] =  st * cm;  o[5] = -st * sm;   // u10
        o[6] =  ct * cp;  o[7] =  ct * sp;   // u11
    }
}

// ---- packed f32x2 helpers ----
__device__ __forceinline__ unsigned long long f2u(float2 v) {
    unsigned long long r;
    asm("mov.b64 %0, {%1,%2};" : "=l"(r) : "f"(v.x), "f"(v.y));
    return r;
}
__device__ __forceinline__ float2 u2f(unsigned long long r) {
    float2 v;
    asm("mov.b64 {%0,%1}, %2;" : "=f"(v.x), "=f"(v.y) : "l"(r));
    return v;
}
__device__ __forceinline__ float2 fma2(float2 a, float2 b, float2 c) {
    unsigned long long r, ua = f2u(a), ub = f2u(b), uc = f2u(c);
    asm("fma.rn.f32x2 %0, %1, %2, %3;" : "=l"(r) : "l"(ua), "l"(ub), "l"(uc));
    return u2f(r);
}
__device__ __forceinline__ float2 mul2(float2 a, float2 b) {
    unsigned long long r, ua = f2u(a), ub = f2u(b);
    asm("mul.rn.f32x2 %0, %1, %2;" : "=l"(r) : "l"(ua), "l"(ub));
    return u2f(r);
}
__device__ __forceinline__ float2 sw2(float2 a) { return make_float2(a.y, a.x); }
__device__ __forceinline__ float2 shfl64(float2 v, int src) {
    unsigned long long u = f2u(v);
    u = __shfl_sync(FULL, u, src);
    return u2f(u);
}
__device__ __forceinline__ float2 shflx64(float2 v, int m) {
    unsigned long long u = f2u(v);
    u = __shfl_xor_sync(FULL, u, m);
    return u2f(u);
}

// logical->physical register index map; advances by gray5 after each CNOT perm
template <int STAGE>
__device__ __forceinline__ int MP(int m) {
    if (STAGE == 0) return m;
    int g = (m ^ (m >> 1)) & 31;
    if (STAGE == 1) return g;
    return (g ^ (g >> 1)) & 31;
}

template <int STAGE>
__device__ __forceinline__ void rot_layer(float2 (&v)[32], int l, int lane) {
    #pragma unroll
    for (int w = 0; w < NW; ++w) {
        const float* gp = &g_rot[(l * NW + w) * 8];
        const float u00r = __ldg(gp + 0), u00i = __ldg(gp + 1);
        const float u01r = __ldg(gp + 2), u01i = __ldg(gp + 3);
        const float u10r = __ldg(gp + 4), u10i = __ldg(gp + 5);
        const float u11r = __ldg(gp + 6), u11i = __ldg(gp + 7);
        if (w < 5) {
            // cross-lane: lane bit q
            const int q = 4 - w;
            const int bit = (lane >> q) & 1;
            const float ar = bit ? u11r : u00r, ai = bit ? u11i : u00i;
            const float br = bit ? u10r : u01r, bi = bit ? u10i : u01i;
            const float2 AR = make_float2(ar, ar), AI = make_float2(-ai, ai);
            const float2 BR = make_float2(br, br), BI = make_float2(-bi, bi);
            #pragma unroll
            for (int m = 0; m < 32; ++m) {
                float2 mine = v[m];
                float2 th = shflx64(mine, 1 << q);
                v[m] = fma2(BI, sw2(th),
                       fma2(BR, th,
                       fma2(AI, sw2(mine),
                       mul2(AR, mine))));
            }
        } else {
            // local: register bit p, via logical->physical map
            const int p = 9 - w;
            const float2 U00R = make_float2(u00r, u00r), U00I = make_float2(-u00i, u00i);
            const float2 U01R = make_float2(u01r, u01r), U01I = make_float2(-u01i, u01i);
            const float2 U10R = make_float2(u10r, u10r), U10I = make_float2(-u10i, u10i);
            const float2 U11R = make_float2(u11r, u11r), U11I = make_float2(-u11i, u11i);
            #pragma unroll
            for (int m = 0; m < 32; ++m) {
                if (m & (1 << p)) continue;
                const int i0 = MP<STAGE>(m), i1 = MP<STAGE>(m | (1 << p));
                float2 a0 = v[i0], a1 = v[i1];
                float2 a0s = sw2(a0), a1s = sw2(a1);
                v[i0] = fma2(U01I, a1s, fma2(U01R, a1, fma2(U00I, a0s, mul2(U00R, a0))));
                v[i1] = fma2(U11I, a1s, fma2(U11R, a1, fma2(U10I, a0s, mul2(U10R, a0))));
            }
        }
    }
}

// CNOT chain: new[j] = old[gray10(j)].  Split over (lane || local):
//   dest lane L reads src lane gray5(L); src local = gray5(J) ^ (L0<<4).
// Implemented as: source-side parity-conditional half-swap (popc parity of the
// source lane equals the destination's L0 since parity(gray5(L)) = L0),
// an in-place lane shuffle, and the local gray5 absorbed into the next
// STAGE's logical->physical index map.
template <int STAGE>
__device__ __forceinline__ void cnot_perm(float2 (&v)[32], int lane) {
    const bool par = (__popc(lane) & 1) != 0;
    #pragma unroll
    for (int k = 0; k < 16; ++k) {
        const int a = MP<STAGE>(k), b2 = MP<STAGE>(k ^ 16);
        float2 t = v[a];
        v[a]  = par ? v[b2] : v[a];
        v[b2] = par ? t : v[b2];
    }
    const int src = (lane ^ (lane >> 1)) & 31;
    #pragma unroll
    for (int j = 0; j < 32; ++j) v[j] = shfl64(v[j], src);
}

__global__ __launch_bounds__(128) void qreg_kernel(
    const float* __restrict__ x,        // (B, 10)
    const float* __restrict__ head_w,   // (20,)
    const float* __restrict__ head_b,   // (1,)
    float* __restrict__ out,            // (B,)
    int B)
{
    const int lane = threadIdx.x & 31;
    const int warp = threadIdx.x >> 5;
    const int b = blockIdx.x * 4 + warp;
    if (b >= B) return;

    float2 v[32];
    #pragma unroll
    for (int m = 0; m < 32; ++m) v[m] = make_float2(0.f, 0.f);
    if (lane == 0) v[0] = make_float2(1.f, 0.f);

    const float xv = (lane < NW) ? x[b * NW + lane] : 0.f;

    // ---- RY encoding ----
    #pragma unroll
    for (int w = 0; w < 5; ++w) {           // cross-lane wires
        const float a = __shfl_sync(FULL, xv, w);
        float c, s;
        __sincosf(0.5f * a, &s, &c);
        const int q = 4 - w;
        const float beta = ((lane >> q) & 1) ? s : -s;
        const float2 C = make_float2(c, c), Bv = make_float2(beta, beta);
        #pragma unroll
        for (int m = 0; m < 32; ++m) {
            float2 th = shflx64(v[m], 1 << q);
            v[m] = fma2(Bv, th, mul2(C, v[m]));
        }
    }
    #pragma unroll
    for (int w = 5; w < NW; ++w) {          // local wires
        const float a = __shfl_sync(FULL, xv, w);
        float c, s;
        __sincosf(0.5f * a, &s, &c);
        const int p = 9 - w;
        const float2 C = make_float2(c, c), S = make_float2(s, s), nS = make_float2(-s, -s);
        #pragma unroll
        for (int m = 0; m < 32; ++m) {
            if (m & (1 << p)) continue;
            const int m1 = m | (1 << p);
            float2 a0 = v[m], a1 = v[m1];
            v[m]  = fma2(nS, a1, mul2(C, a0));
            v[m1] = fma2(S,  a0, mul2(C, a1));
        }
    }

    // ---- 2 layers: Rot gates + fused CNOT chain ----
    rot_layer<0>(v, 0, lane);
    cnot_perm<0>(v, lane);
    rot_layer<1>(v, 1, lane);
    cnot_perm<1>(v, lane);

    // ---- fused measurement + linear head (state map = stage 2) ----
    float partial = 0.f;

    // Z features
    float D0 = 0.f, D1 = 0.f, D2 = 0.f, D3 = 0.f, D4 = 0.f, prtot = 0.f;
    #pragma unroll
    for (int m = 0; m < 32; ++m) {
        const float2 a = v[MP<2>(m)];
        const float pr = a.x * a.x + a.y * a.y;
        prtot += pr;
        D0 += (m & 1)  ? -pr : pr;
        D1 += (m & 2)  ? -pr : pr;
        D2 += (m & 4)  ? -pr : pr;
        D3 += (m & 8)  ? -pr : pr;
        D4 += (m & 16) ? -pr : pr;
    }
    partial += __ldg(&head_w[9]) * D0 + __ldg(&head_w[8]) * D1 + __ldg(&head_w[7]) * D2
             + __ldg(&head_w[6]) * D3 + __ldg(&head_w[5]) * D4;
    float zh = 0.f;
    #pragma unroll
    for (int q = 0; q < 5; ++q) {
        const float wz = __ldg(&head_w[4 - q]);
        zh += ((lane >> q) & 1) ? -wz : wz;
    }
    partial += prtot * zh;

    // X features, local wires (p = 0..4 -> wires 9..5)
    #pragma unroll
    for (int p = 0; p < 5; ++p) {
        float acc = 0.f;
        #pragma unroll
        for (int m = 0; m < 32; ++m) {
            if (m & (1 << p)) continue;
            const float2 a0 = v[MP<2>(m)], a1 = v[MP<2>(m | (1 << p))];
            acc += a0.x * a1.x + a0.y * a1.y;
        }
        partial += 2.f * __ldg(&head_w[NW + 9 - p]) * acc;
    }

    // X features, cross-lane wires (q = 0..4 -> wires 4..0)
    #pragma unroll
    for (int q = 0; q < 5; ++q) {
        float acc = 0.f;
        #pragma unroll
        for (int m = 0; m < 32; ++m) {
            const float2 th = shflx64(v[m], 1 << q);
            acc += v[m].x * th.x + v[m].y * th.y;
        }
        partial += __ldg(&head_w[NW + 4 - q]) * acc;   // pair-double-count = the 2x factor
    }

    // warp reduction -> output
    #pragma unroll
    for (int o = 16; o > 0; o >>= 1)
        partial += __shfl_xor_sync(FULL, partial, o);
    if (lane == 0) out[b] = partial + __ldg(head_b);
}

extern "C" void kernel_launch(void* const* d_in, const int* in_sizes, int n_in,
                              void* d_out, int out_size) {
    const float* x      = (const float*)d_in[0];  // (B,10)
    const float* params = (const float*)d_in[1];  // (60,)
    const float* hw     = (const float*)d_in[2];  // (20,)
    const float* hb     = (const float*)d_in[3];  // (1,)
    float* out = (float*)d_out;
    const int B = in_sizes[0] / NW;               // 4096

    prep_kernel<<<1, 32>>>(params);
    const int warps_per_blk = 4;
    const int blocks = (B + warps_per_blk - 1) / warps_per_blk;
    qreg_kernel<<<blocks, warps_per_blk * 32>>>(x, hw, hb, out, B);
}

// round 5
// speedup vs baseline: 4.1017x; 1.6623x over previous
#include <cuda_runtime.h>

#define FULL 0xffffffffu
#define NW 10

// Full Rot matrices for both layers: per gate 8 floats {u00r,u00i,u01r,u01i,u10r,u10i,u11r,u11i}
__device__ float g_rot[2 * NW * 8];

__global__ void prep_kernel(const float* __restrict__ params) {
    int g = threadIdx.x;
    if (g < 2 * NW) {
        float phi = params[g * 3 + 0], th = params[g * 3 + 1], om = params[g * 3 + 2];
        float ct, st, cp, sp, cm, sm;
        sincosf(0.5f * th, &st, &ct);
        sincosf(0.5f * (phi + om), &sp, &cp);
        sincosf(0.5f * (phi - om), &sm, &cm);
        float* o = &g_rot[g * 8];
        // Rot = RZ(om) RY(th) RZ(phi)
        o[0] =  ct * cp;  o[1] = -ct * sp;   // u00
        o[2] = -st * cm;  o[3] = -st * sm;   // u01
        o[4] =  st * cm;  o[5] = -st * sm;   // u10
        o[6] =  ct * cp;  o[7] =  ct * sp;   // u11
    }
}

// ---- packed f32x2 helpers ----
__device__ __forceinline__ unsigned long long f2u(float2 v) {
    unsigned long long r;
    asm("mov.b64 %0, {%1,%2};" : "=l"(r) : "f"(v.x), "f"(v.y));
    return r;
}
__device__ __forceinline__ float2 u2f(unsigned long long r) {
    float2 v;
    asm("mov.b64 {%0,%1}, %2;" : "=f"(v.x), "=f"(v.y) : "l"(r));
    return v;
}
__device__ __forceinline__ float2 fma2(float2 a, float2 b, float2 c) {
    unsigned long long r, ua = f2u(a), ub = f2u(b), uc = f2u(c);
    asm("fma.rn.f32x2 %0, %1, %2, %3;" : "=l"(r) : "l"(ua), "l"(ub), "l"(uc));
    return u2f(r);
}
__device__ __forceinline__ float2 mul2(float2 a, float2 b) {
    unsigned long long r, ua = f2u(a), ub = f2u(b);
    asm("mul.rn.f32x2 %0, %1, %2;" : "=l"(r) : "l"(ua), "l"(ub));
    return u2f(r);
}
__device__ __forceinline__ float2 sw2(float2 a) { return make_float2(a.y, a.x); }
__device__ __forceinline__ float2 shfl64(float2 v, int src) {
    unsigned long long u = f2u(v);
    u = __shfl_sync(FULL, u, src);
    return u2f(u);
}
__device__ __forceinline__ float2 shflx64(float2 v, int m) {
    unsigned long long u = f2u(v);
    u = __shfl_xor_sync(FULL, u, m);
    return u2f(u);
}
// complex multiply (2 packed ops)
__device__ __forceinline__ float2 cmul(float2 a, float2 b) {
    return fma2(make_float2(-a.y, a.y), sw2(b),
                mul2(make_float2(a.x, a.x), b));
}
__device__ __forceinline__ int gray5(int m) { return (m ^ (m >> 1)) & 31; }

// layer-2 full-Rot gates, identity logical->physical map
__device__ __forceinline__ void rot_layer2(float2 (&v)[32], int lane) {
    #pragma unroll
    for (int w = 0; w < NW; ++w) {
        const float* gp = &g_rot[(NW + w) * 8];
        const float u00r = __ldg(gp + 0), u00i = __ldg(gp + 1);
        const float u01r = __ldg(gp + 2), u01i = __ldg(gp + 3);
        const float u10r = __ldg(gp + 4), u10i = __ldg(gp + 5);
        const float u11r = __ldg(gp + 6), u11i = __ldg(gp + 7);
        if (w < 5) {
            // cross-lane: lane bit q
            const int q = 4 - w;
            const int bit = (lane >> q) & 1;
            const float ar = bit ? u11r : u00r, ai = bit ? u11i : u00i;
            const float br = bit ? u10r : u01r, bi = bit ? u10i : u01i;
            const float2 AR = make_float2(ar, ar), AI = make_float2(-ai, ai);
            const float2 BR = make_float2(br, br), BI = make_float2(-bi, bi);
            #pragma unroll
            for (int m = 0; m < 32; ++m) {
                float2 mine = v[m];
                float2 th = shflx64(mine, 1 << q);
                v[m] = fma2(BI, sw2(th),
                       fma2(BR, th,
                       fma2(AI, sw2(mine),
                       mul2(AR, mine))));
            }
        } else {
            // local: register bit p (identity map)
            const int p = 9 - w;
            const float2 U00R = make_float2(u00r, u00r), U00I = make_float2(-u00i, u00i);
            const float2 U01R = make_float2(u01r, u01r), U01I = make_float2(-u01i, u01i);
            const float2 U10R = make_float2(u10r, u10r), U10I = make_float2(-u10i, u10i);
            const float2 U11R = make_float2(u11r, u11r), U11I = make_float2(-u11i, u11i);
            #pragma unroll
            for (int m = 0; m < 32; ++m) {
                if (m & (1 << p)) continue;
                const int m1 = m | (1 << p);
                float2 a0 = v[m], a1 = v[m1];
                float2 a0s = sw2(a0), a1s = sw2(a1);
                v[m]  = fma2(U01I, a1s, fma2(U01R, a1, fma2(U00I, a0s, mul2(U00R, a0))));
                v[m1] = fma2(U11I, a1s, fma2(U11R, a1, fma2(U10I, a0s, mul2(U10R, a0))));
            }
        }
    }
}

__global__ __launch_bounds__(128) void qreg_kernel(
    const float* __restrict__ x,        // (B, 10)
    const float* __restrict__ head_w,   // (20,)
    const float* __restrict__ head_b,   // (1,)
    float* __restrict__ out,            // (B,)
    int B)
{
    const int lane = threadIdx.x & 31;
    const int warp = threadIdx.x >> 5;
    const int b = blockIdx.x * 4 + warp;
    if (b >= B) return;

    // ---- Phase A: per-wire 1-qubit states (alpha,beta) = (Rot1_w @ RY(x_w)) column 0 ----
    float2 alpha, beta;
    {
        const float xv = (lane < NW) ? x[b * NW + lane] : 0.f;
        float cx, sx;
        __sincosf(0.5f * xv, &sx, &cx);
        const int gl = (lane < NW) ? lane : 0;
        const float* gp = &g_rot[gl * 8];
        const float u00r = __ldg(gp + 0), u00i = __ldg(gp + 1);
        const float u01r = __ldg(gp + 2), u01i = __ldg(gp + 3);
        const float u10r = __ldg(gp + 4), u10i = __ldg(gp + 5);
        const float u11r = __ldg(gp + 6), u11i = __ldg(gp + 7);
        alpha = make_float2(u00r * cx + u01r * sx, u00i * cx + u01i * sx);
        beta  = make_float2(u10r * cx + u11r * sx, u10i * cx + u11i * sx);
    }

    // Build the state AFTER CNOT chain #1 directly (perm absorbed):
    //   new[(L<<5)|J] = prod_w f_w(bit_w(src)), src_lane = gray5(L),
    //   src_local = gray5(J) ^ (L0<<4),  L0 = lane & 1.
    const int gL = gray5(lane);
    float2 F;
    {
        #pragma unroll
        for (int w = 0; w < 5; ++w) {
            const float2 a  = shfl64(alpha, w);
            const float2 bb = shfl64(beta, w);
            const float2 f = ((gL >> (4 - w)) & 1) ? bb : a;
            F = (w == 0) ? f : cmul(F, f);
        }
    }

    // local factor tables, wires 5..9 (local bit k <-> wire 9-k)
    float2 fa[5], fb[5];
    #pragma unroll
    for (int k = 0; k < 5; ++k) {
        fa[k] = shfl64(alpha, 9 - k);
        fb[k] = shfl64(beta,  9 - k);
    }
    const int L0 = lane & 1;
    const float2 c0 = L0 ? fb[4] : fa[4];
    const float2 c1 = L0 ? fa[4] : fb[4];
    const float2 top0 = cmul(F, c0), top1 = cmul(F, c1);

    float2 T01[4], TT[8];
    #pragma unroll
    for (int i = 0; i < 4; ++i)
        T01[i] = cmul((i & 2) ? fb[1] : fa[1], (i & 1) ? fb[0] : fa[0]);
    #pragma unroll
    for (int i = 0; i < 8; ++i) {
        const float2 t23 = cmul((i & 2) ? fb[3] : fa[3], (i & 1) ? fb[2] : fa[2]);
        TT[i] = cmul((i & 4) ? top1 : top0, t23);
    }

    float2 v[32];
    #pragma unroll
    for (int r = 0; r < 32; ++r) {
        const int y = gray5(r);          // compile-time constant per r
        v[r] = cmul(TT[y >> 2], T01[y & 3]);
    }

    // ---- Phase B: layer-2 full Rot gates ----
    rot_layer2(v, lane);

    // ---- Phase C: CNOT chain #2 ----
    // source-side parity half-swap + lane shuffle; local gray absorbed into
    // measurement indexing (logical m -> physical gray5(m)).
    {
        const bool par = (__popc(lane) & 1) != 0;
        #pragma unroll
        for (int k = 0; k < 16; ++k) {
            float2 t = v[k];
            v[k]      = par ? v[k ^ 16] : v[k];
            v[k ^ 16] = par ? t : v[k ^ 16];
        }
        #pragma unroll
        for (int j = 0; j < 32; ++j) v[j] = shfl64(v[j], gL);
    }

    // ---- fused measurement + linear head (logical m at physical gray5(m)) ----
    float partial = 0.f;

    // Z features
    {
        float D0 = 0.f, D1 = 0.f, D2 = 0.f, D3 = 0.f, D4 = 0.f, prtot = 0.f;
        #pragma unroll
        for (int m = 0; m < 32; ++m) {
            const float2 a = v[gray5(m)];
            const float pr = a.x * a.x + a.y * a.y;
            prtot += pr;
            D0 += (m & 1)  ? -pr : pr;
            D1 += (m & 2)  ? -pr : pr;
            D2 += (m & 4)  ? -pr : pr;
            D3 += (m & 8)  ? -pr : pr;
            D4 += (m & 16) ? -pr : pr;
        }
        partial += __ldg(&head_w[9]) * D0 + __ldg(&head_w[8]) * D1 + __ldg(&head_w[7]) * D2
                 + __ldg(&head_w[6]) * D3 + __ldg(&head_w[5]) * D4;
        float zh = 0.f;
        #pragma unroll
        for (int q = 0; q < 5; ++q) {
            const float wz = __ldg(&head_w[4 - q]);
            zh += ((lane >> q) & 1) ? -wz : wz;
        }
        partial += prtot * zh;
    }

    // X features, local wires (local bit p <-> wire 9-p)
    #pragma unroll
    for (int p = 0; p < 5; ++p) {
        float acc = 0.f;
        #pragma unroll
        for (int m = 0; m < 32; ++m) {
            if (m & (1 << p)) continue;
            const float2 a0 = v[gray5(m)], a1 = v[gray5(m | (1 << p))];
            acc += a0.x * a1.x + a0.y * a1.y;
        }
        partial += 2.f * __ldg(&head_w[NW + 9 - p]) * acc;
    }

    // X features, cross-lane wires (lane bit q <-> wire 4-q)
    #pragma unroll
    for (int q = 0; q < 5; ++q) {
        float acc = 0.f;
        #pragma unroll
        for (int m = 0; m < 32; ++m) {
            const float2 th = shflx64(v[m], 1 << q);
            acc += v[m].x * th.x + v[m].y * th.y;
        }
        partial += __ldg(&head_w[NW + 4 - q]) * acc;   // pair double-count = the 2x factor
    }

    // warp reduction -> output
    #pragma unroll
    for (int o = 16; o > 0; o >>= 1)
        partial += __shfl_xor_sync(FULL, partial, o);
    if (lane == 0) out[b] = partial + __ldg(head_b);
}

extern "C" void kernel_launch(void* const* d_in, const int* in_sizes, int n_in,
                              void* d_out, int out_size) {
    const float* x      = (const float*)d_in[0];  // (B,10)
    const float* params = (const float*)d_in[1];  // (60,)
    const float* hw     = (const float*)d_in[2];  // (20,)
    const float* hb     = (const float*)d_in[3];  // (1,)
    float* out = (float*)d_out;
    const int B = in_sizes[0] / NW;               // 4096

    prep_kernel<<<1, 32>>>(params);
    const int warps_per_blk = 4;
    const int blocks = (B + warps_per_blk - 1) / warps_per_blk;
    qreg_kernel<<<blocks, warps_per_blk * 32>>>(x, hw, hb, out, B);
}

// round 6
// speedup vs baseline: 11.8240x; 2.8827x over previous
#include <cuda_runtime.h>

#define NW 10

// layer-1 Rot matrices (per wire, 8 floats) for per-sample (alpha,beta)
__device__ float  g_rot1[NW * 8];
// per BIT k (bit k <-> wire 9-k): M = U^H P U for the layer-2 gate on that bit
__device__ float2 g_MZ[NW * 4];   // [k*4 + r*2 + c]
__device__ float2 g_MX[NW * 4];

__global__ void prep_kernel(const float* __restrict__ params) {
    int k = threadIdx.x;
    if (k < NW) {
        // layer-1 Rot for wire k
        float phi = params[k * 3 + 0], th = params[k * 3 + 1], om = params[k * 3 + 2];
        float ct, st, cp, sp, cm, sm;
        sincosf(0.5f * th, &st, &ct);
        sincosf(0.5f * (phi + om), &sp, &cp);
        sincosf(0.5f * (phi - om), &sm, &cm);
        float* o = &g_rot1[k * 8];
        o[0] =  ct * cp;  o[1] = -ct * sp;
        o[2] = -st * cm;  o[3] = -st * sm;
        o[4] =  st * cm;  o[5] = -st * sm;
        o[6] =  ct * cp;  o[7] =  ct * sp;

        // layer-2 gate on bit k is the Rot of wire w = 9-k
        int w = 9 - k;
        float phi2 = params[(NW + w) * 3 + 0], th2 = params[(NW + w) * 3 + 1], om2 = params[(NW + w) * 3 + 2];
        sincosf(0.5f * th2, &st, &ct);
        sincosf(0.5f * (phi2 + om2), &sp, &cp);
        sincosf(0.5f * (phi2 - om2), &sm, &cm);
        // U[row][col], complex
        float U[2][2][2];
        U[0][0][0] =  ct * cp;  U[0][0][1] = -ct * sp;
        U[0][1][0] = -st * cm;  U[0][1][1] = -st * sm;
        U[1][0][0] =  st * cm;  U[1][0][1] = -st * sm;
        U[1][1][0] =  ct * cp;  U[1][1][1] =  ct * sp;
        // MZ[r][c] = conj(U[0][r])*U[0][c] - conj(U[1][r])*U[1][c]
        // MX[r][c] = conj(U[0][r])*U[1][c] + conj(U[1][r])*U[0][c]
        for (int r = 0; r < 2; ++r)
            for (int c = 0; c < 2; ++c) {
                float a0r = U[0][r][0], a0i = U[0][r][1];
                float a1r = U[1][r][0], a1i = U[1][r][1];
                float b0r = U[0][c][0], b0i = U[0][c][1];
                float b1r = U[1][c][0], b1i = U[1][c][1];
                // conj(a0)*b0
                float z0r = a0r * b0r + a0i * b0i, z0i = a0r * b0i - a0i * b0r;
                // conj(a1)*b1
                float z1r = a1r * b1r + a1i * b1i, z1i = a1r * b1i - a1i * b1r;
                g_MZ[k * 4 + r * 2 + c] = make_float2(z0r - z1r, z0i - z1i);
                // conj(a0)*b1
                float y0r = a0r * b1r + a0i * b1i, y0i = a0r * b1i - a0i * b1r;
                // conj(a1)*b0
                float y1r = a1r * b0r + a1i * b0i, y1i = a1r * b0i - a1i * b0r;
                g_MX[k * 4 + r * 2 + c] = make_float2(y0r + y1r, y0i + y1i);
            }
    }
}

// ---- packed f32x2 complex helpers ----
__device__ __forceinline__ unsigned long long f2u(float2 v) {
    unsigned long long r;
    asm("mov.b64 %0, {%1,%2};" : "=l"(r) : "f"(v.x), "f"(v.y));
    return r;
}
__device__ __forceinline__ float2 u2f(unsigned long long r) {
    float2 v;
    asm("mov.b64 {%0,%1}, %2;" : "=f"(v.x), "=f"(v.y) : "l"(r));
    return v;
}
__device__ __forceinline__ float2 fma2(float2 a, float2 b, float2 c) {
    unsigned long long r, ua = f2u(a), ub = f2u(b), uc = f2u(c);
    asm("fma.rn.f32x2 %0, %1, %2, %3;" : "=l"(r) : "l"(ua), "l"(ub), "l"(uc));
    return u2f(r);
}
__device__ __forceinline__ float2 mul2(float2 a, float2 b) {
    unsigned long long r, ua = f2u(a), ub = f2u(b);
    asm("mul.rn.f32x2 %0, %1, %2;" : "=l"(r) : "l"(ua), "l"(ub));
    return u2f(r);
}
__device__ __forceinline__ float2 sw2(float2 a) { return make_float2(a.y, a.x); }
// a*b
__device__ __forceinline__ float2 cmul(float2 a, float2 b) {
    return fma2(make_float2(-a.y, a.y), sw2(b), mul2(make_float2(a.x, a.x), b));
}
// a*b + c
__device__ __forceinline__ float2 cmula(float2 a, float2 b, float2 c) {
    return fma2(make_float2(-a.y, a.y), sw2(b), fma2(make_float2(a.x, a.x), b, c));
}
// conj(a)*b
__device__ __forceinline__ float2 cjmul(float2 a, float2 b) {
    return fma2(make_float2(a.y, -a.y), sw2(b), mul2(make_float2(a.x, a.x), b));
}
// conj(a)*b + c
__device__ __forceinline__ float2 cjmula(float2 a, float2 b, float2 c) {
    return fma2(make_float2(a.y, -a.y), sw2(b), fma2(make_float2(a.x, a.x), b, c));
}
// real*complex + complex
__device__ __forceinline__ float2 sra(float s, float2 a, float2 c) {
    return fma2(make_float2(s, s), a, c);
}

__global__ __launch_bounds__(32) void qreg_kernel(
    const float* __restrict__ x,        // (B, 10)
    const float* __restrict__ head_w,   // (20,)
    const float* __restrict__ head_b,   // (1,)
    float* __restrict__ out,            // (B,)
    int B)
{
    const int b = blockIdx.x * 32 + threadIdx.x;
    if (b >= B) return;

    // ---- per-bit 1-qubit factors g_k(0), g_k(1): bit k <-> wire 9-k ----
    float2 g0[NW], g1[NW];
    #pragma unroll
    for (int w = 0; w < NW; ++w) {
        float cx, sx;
        __sincosf(0.5f * __ldg(&x[b * NW + w]), &sx, &cx);
        const float* gp = &g_rot1[w * 8];
        float2 al = make_float2(__ldg(gp + 0) * cx + __ldg(gp + 2) * sx,
                                __ldg(gp + 1) * cx + __ldg(gp + 3) * sx);
        float2 be = make_float2(__ldg(gp + 4) * cx + __ldg(gp + 6) * sx,
                                __ldg(gp + 5) * cx + __ldg(gp + 7) * sx);
        g0[9 - w] = al;
        g1[9 - w] = be;
    }

    // ---- identity suffix sweep: S_k diag, REAL 2-vector; S_10 = (1,0) ----
    float sA[11], sB[11];
    sA[10] = 1.f; sB[10] = 0.f;
    #pragma unroll
    for (int k = 9; k >= 0; --k) {
        const float n0 = g0[k].x * g0[k].x + g0[k].y * g0[k].y;
        const float n1 = g1[k].x * g1[k].x + g1[k].y * g1[k].y;
        sA[k] = n0 * sA[k + 1] + n1 * sB[k + 1];
        sB[k] = n1 * sA[k + 1] + n0 * sB[k + 1];
    }

    // ---- all-Z suffix sweep: SZ_k = E_k^Z ... E_9^Z v (4 complex each) ----
    float2 Zs[NW][4];
    {
        float2 r0 = make_float2(1.f, 0.f), r1 = make_float2(0.f, 0.f);
        float2 r2 = make_float2(0.f, 0.f), r3 = make_float2(0.f, 0.f);
        #pragma unroll
        for (int k = 9; k >= 0; --k) {
            const float2 ga = g0[k], gb = g1[k];
            // h[a'][b] = sum_{b'} conj(g(a'^b')) r[(b',b)]
            const float2 h00 = cjmula(ga, r0, cjmul(gb, r2));
            const float2 h01 = cjmula(ga, r1, cjmul(gb, r3));
            const float2 h10 = cjmula(gb, r0, cjmul(ga, r2));
            const float2 h11 = cjmula(gb, r1, cjmul(ga, r3));
            // t[(a',a)] = sum_b g(a^b) h[a'][b]
            const float2 t00 = cmula(ga, h00, cmul(gb, h01));
            const float2 t01 = cmula(gb, h00, cmul(ga, h01));
            const float2 t10 = cmula(ga, h10, cmul(gb, h11));
            const float2 t11 = cmula(gb, h10, cmul(ga, h11));
            r0 = cmul(__ldg(&g_MZ[k * 4 + 0]), t00);
            r1 = cmul(__ldg(&g_MZ[k * 4 + 1]), t01);
            r2 = cmul(__ldg(&g_MZ[k * 4 + 2]), t10);
            r3 = cmul(__ldg(&g_MZ[k * 4 + 3]), t11);
            Zs[k][0] = r0; Zs[k][1] = r1; Zs[k][2] = r2; Zs[k][3] = r3;
        }
    }

    // ---- prefix sweep with fused features ----
    float acc = 0.f;
    float2 l0 = make_float2(1.f, 0.f), l1 = make_float2(1.f, 0.f);
    float2 l2 = make_float2(1.f, 0.f), l3 = make_float2(1.f, 0.f);
    #pragma unroll
    for (int k = 0; k < NW; ++k) {
        const float2 ga = g0[k], gb = g1[k];

        // Z feature, wire 9-k:  F = L_k . SZ_k
        {
            float2 d = cmul(l0, Zs[k][0]);
            d = cmula(l1, Zs[k][1], d);
            d = cmula(l2, Zs[k][2], d);
            d = cmula(l3, Zs[k][3], d);
            acc += __ldg(&head_w[9 - k]) * d.x;
        }

        if (k <= 8) {
            // mu = L_k * E_k^X   (left-apply)
            float2 p0 = cmul(l0, __ldg(&g_MX[k * 4 + 0]));
            float2 p1 = cmul(l1, __ldg(&g_MX[k * 4 + 1]));
            float2 p2 = cmul(l2, __ldg(&g_MX[k * 4 + 2]));
            float2 p3 = cmul(l3, __ldg(&g_MX[k * 4 + 3]));
            float2 h00 = cmula(p0, ga, cmul(p1, gb));
            float2 h01 = cmula(p0, gb, cmul(p1, ga));
            float2 h10 = cmula(p2, ga, cmul(p3, gb));
            float2 h11 = cmula(p2, gb, cmul(p3, ga));
            float2 m0 = cjmula(ga, h00, cjmul(gb, h10));
            float2 m1 = cjmula(ga, h01, cjmul(gb, h11));
            float2 m2 = cjmula(gb, h00, cjmul(ga, h10));
            float2 m3 = cjmula(gb, h01, cjmul(ga, h11));

            if (k == 0) {
                // X feature, wire 9 (X on bit 0 only): F = mu . S_1 (diag)
                acc += __ldg(&head_w[19]) * (m0.x * sA[1] + m3.x * sB[1]);
            }

            // nu = mu * E_{k+1}^X ; X-pair feature, wire 8-k
            const float2 gc = g0[k + 1], gd = g1[k + 1];
            float2 q0 = cmul(m0, __ldg(&g_MX[(k + 1) * 4 + 0]));
            float2 q1 = cmul(m1, __ldg(&g_MX[(k + 1) * 4 + 1]));
            float2 q2 = cmul(m2, __ldg(&g_MX[(k + 1) * 4 + 2]));
            float2 q3 = cmul(m3, __ldg(&g_MX[(k + 1) * 4 + 3]));
            float2 j00 = cmula(q0, gc, cmul(q1, gd));
            float2 j01 = cmula(q0, gd, cmul(q1, gc));
            float2 j10 = cmula(q2, gc, cmul(q3, gd));
            float2 j11 = cmula(q2, gd, cmul(q3, gc));
            float2 n0 = cjmula(gc, j00, cjmul(gd, j10));
            float2 n3 = cjmula(gd, j01, cjmul(gc, j11));
            acc += __ldg(&head_w[18 - k]) * (n0.x * sA[k + 2] + n3.x * sB[k + 2]);

            // advance: L_{k+1} = L_k * E_k^I  (only diag(L) contributes through M=I)
            const float n0g = ga.x * ga.x + ga.y * ga.y;
            const float n1g = gb.x * gb.x + gb.y * gb.y;
            const float2 e01 = cjmul(ga, gb);                 // conj(g0)*g1
            const float2 e10 = make_float2(e01.x, -e01.y);    // conj(g1)*g0
            const float2 d0 = l0, d1 = l3;
            l0 = sra(n0g, d0, mul2(make_float2(n1g, n1g), d1));
            l3 = sra(n1g, d0, mul2(make_float2(n0g, n0g), d1));
            l1 = cmula(d0, e01, cmul(d1, e10));
            l2 = cmula(d0, e10, cmul(d1, e01));
        }
    }

    out[b] = acc + __ldg(head_b);
}

extern "C" void kernel_launch(void* const* d_in, const int* in_sizes, int n_in,
                              void* d_out, int out_size) {
    const float* x      = (const float*)d_in[0];  // (B,10)
    const float* params = (const float*)d_in[1];  // (60,)
    const float* hw     = (const float*)d_in[2];  // (20,)
    const float* hb     = (const float*)d_in[3];  // (1,)
    float* out = (float*)d_out;
    const int B = in_sizes[0] / NW;               // 4096

    prep_kernel<<<1, 32>>>(params);
    qreg_kernel<<<(B + 31) / 32, 32>>>(x, hw, hb, out, B);
}